// round 15
// baseline (speedup 1.0000x reference)
#include <cuda_runtime.h>

// ============================================================================
// HybridLoss: B=2, T=4, N=4096  —  2 launches with PDL overlap.
// DIST (dual-pass, zero-shuffle): block = 1024 rows x 128 cols, 128 thr;
//   grid (4,32,16) = 2048 blocks (~14/SM). Total staging work invariant
//   under the column split (one staging per column per rowblk).
//   pass 0: rows=pred, cols=tgt  -> row-min = min_p -> g_enc_p
//   pass 1: rows=tgt,  cols=pred -> row-min = min_t -> g_enc_t
//   Row bias rw added ONCE at publish: 3 fma2 + 2 FMNMX per 2 distances.
// EPILOGUE: grid 8 x 1024 thr, PDL dependent; fused multi-value reductions.
// All device state zero at load and re-zeroed each call (graph-safe).
// ============================================================================

#define ALPHA_C  0.5f
#define INV_TEMP 10.0f
#define BIGF     10000000000.0f
#define THRESHF  1000000000.0f

constexpr int N_  = 4096;
constexpr int BT_ = 8;

constexpr int ROWS_PB = 1024;             // rows per block
constexpr int COLS_PB = 128;              // cols per block (staged once)
constexpr int RPT     = 8;                // rows per thread (4 packed pairs)
constexpr int ROWBLKS = N_ / ROWS_PB;     // 4
constexpr int COLBLKS = N_ / COLS_PB;     // 32

__device__ unsigned g_enc_p[BT_][N_];
__device__ unsigned g_enc_t[BT_][N_];
__device__ float    g_cd[BT_];
__device__ float    g_hd[BT_];
__device__ unsigned g_done;

// ---------------------------------------------------------------------------
__device__ __forceinline__ unsigned enc_desc(float f) {
    unsigned b = __float_as_uint(f);
    unsigned asc = (b & 0x80000000u) ? ~b : (b | 0x80000000u);
    return ~asc;
}
__device__ __forceinline__ float dec_desc(unsigned k) {
    unsigned asc = ~k;
    unsigned b = (asc & 0x80000000u) ? (asc ^ 0x80000000u) : ~asc;
    return __uint_as_float(b);
}

typedef unsigned long long u64;
__device__ __forceinline__ u64 fma2(u64 a, u64 b, u64 c) {
    u64 d; asm("fma.rn.f32x2 %0, %1, %2, %3;" : "=l"(d) : "l"(a), "l"(b), "l"(c));
    return d;
}
__device__ __forceinline__ u64 pack2(float a, float b) {
    u64 r; asm("mov.b64 %0, {%1, %2};" : "=l"(r) : "f"(a), "f"(b));
    return r;
}
__device__ __forceinline__ void unpack2(u64 v, float& a, float& b) {
    asm("mov.b64 {%0, %1}, %2;" : "=f"(a), "=f"(b) : "l"(v));
}

__device__ __forceinline__ bool ldmask(const void* p, int i, int mode) {
    if (mode == 0) return ((const unsigned char*)p)[i] != 0;
    if (mode == 1) return ((const int*)p)[i] != 0;
    return ((const float*)p)[i] != 0.0f;
}

// Per-block mask-dtype detection (warp-0 ballot of 32 samples of the ~95%-
// dense padding mask). P(all 32 sampled bytes zero for u8 bool) ~ 0.05^32.
__device__ __forceinline__ int detect_mode_block(const unsigned char* pad,
                                                 int tid, int* s_mode) {
    if (tid < 32) {
        const unsigned b1 = __ballot_sync(0xffffffffu, pad[4 * tid + 1] != 0);
        const unsigned b2 = __ballot_sync(0xffffffffu, pad[4 * tid + 2] != 0);
        if (tid == 0) *s_mode = b1 ? 0 : (b2 ? 2 : 1);
    }
    __syncthreads();
    return *s_mode;
}

// ---------------------------------------------------------------------------
// dist: grid (ROWBLKS, COLBLKS, BT_*2), 128 threads.
// ---------------------------------------------------------------------------
__global__ void __launch_bounds__(128) dist_kernel(
    const float* __restrict__ pred, const float* __restrict__ tgt,
    const void* __restrict__ isctl, const void* __restrict__ pad,
    const void* __restrict__ vis)
{
    asm volatile("griddepcontrol.launch_dependents;");

    __shared__ float4 sc[COLS_PB * 2];  // per col: (-2x,-2x,-2y,-2y)(-2z,-2z,w,w)
    __shared__ int    s_mode;

    const int rowblk = blockIdx.x;
    const int colblk = blockIdx.y;
    const int bt     = blockIdx.z >> 1;
    const int pass   = blockIdx.z & 1;
    const int b      = bt >> 2;
    const int tid    = threadIdx.x;
    const int mode   = detect_mode_block((const unsigned char*)pad, tid, &s_mode);

    const float* __restrict__ rows = pass ? tgt  : pred;
    const float* __restrict__ cols = pass ? pred : tgt;
    unsigned* __restrict__ enc = pass ? &g_enc_t[bt][0] : &g_enc_p[bt][0];

    // ---- stage this block's 128 columns (one per thread) -------------------
    {
        const int m = colblk * COLS_PB + tid;
        const float* cp = cols + ((size_t)bt * N_ + m) * 3;
        const float x = cp[0], y = cp[1], z = cp[2];
        const bool msk = !ldmask(isctl, b * N_ + m, mode)
                       &&  ldmask(pad,   b * N_ + m, mode)
                       &&  ldmask(vis,  bt * N_ + m, mode);
        const float cw = fmaf(x, x, fmaf(y, y, z * z)) + (msk ? 0.0f : BIGF);
        sc[2 * tid]     = make_float4(-2.f * x, -2.f * x, -2.f * y, -2.f * y);
        sc[2 * tid + 1] = make_float4(-2.f * z, -2.f * z, cw, cw);
    }

    // ---- this thread's 8 rows (4 packed pairs); rw deferred to publish -----
    u64 px2[4], py2[4], pz2[4];
    float rw[RPT], rmin[RPT];
    const int rbase = rowblk * ROWS_PB + tid * RPT;
#pragma unroll
    for (int q = 0; q < 4; q++) {
        float x[2], y[2], z[2];
#pragma unroll
        for (int h = 0; h < 2; h++) {
            const int row = rbase + q * 2 + h;
            const float* rp = rows + ((size_t)bt * N_ + row) * 3;
            x[h] = rp[0]; y[h] = rp[1]; z[h] = rp[2];
            const bool msk = !ldmask(isctl, b * N_ + row, mode)
                           &&  ldmask(pad,   b * N_ + row, mode)
                           &&  ldmask(vis,  bt * N_ + row, mode);
            rw[q * 2 + h] = fmaf(x[h], x[h], fmaf(y[h], y[h], z[h] * z[h]))
                          + (msk ? 0.0f : BIGF);
            rmin[q * 2 + h] = 3.0e38f;
        }
        px2[q] = pack2(x[0], x[1]);
        py2[q] = pack2(y[0], y[1]);
        pz2[q] = pack2(z[0], z[1]);
    }
    __syncthreads();   // the only barrier

    // ---- pure streaming loop: 128 cols x 8 rows, 3 fma2 + 2 min / 2 dists --
#pragma unroll 4
    for (int c = 0; c < COLS_PB; c++) {
        const u64* cd = reinterpret_cast<const u64*>(&sc[2 * c]);
        const u64 xd = cd[0], yd = cd[1], zd = cd[2], wd = cd[3];
#pragma unroll
        for (int q = 0; q < 4; q++) {
            const u64 acc = fma2(px2[q], xd,
                            fma2(py2[q], yd,
                            fma2(pz2[q], zd, wd)));
            float lo, hi;
            unpack2(acc, lo, hi);
            rmin[q * 2]     = fminf(rmin[q * 2], lo);
            rmin[q * 2 + 1] = fminf(rmin[q * 2 + 1], hi);
        }
    }

    // ---- publish 8 row-mins (row bias added once, outside the loop) --------
#pragma unroll
    for (int r = 0; r < RPT; r++)
        atomicMax(&enc[rbase + r], enc_desc(rmin[r] + rw[r]));
}

// ---------------------------------------------------------------------------
// epilogue (PDL dependent): grid=8 (bt), 1024 threads.
// Fused multi-value block reductions: one smem round handles up to 5 values.
// ---------------------------------------------------------------------------
template <int NV>
__device__ __forceinline__ void blockRedN(float* v, const bool* ismax, float* s) {
    const int w = threadIdx.x >> 5, l = threadIdx.x & 31;
#pragma unroll
    for (int i = 0; i < NV; i++) {
#pragma unroll
        for (int o = 16; o > 0; o >>= 1) {
            const float x = __shfl_xor_sync(0xffffffffu, v[i], o);
            v[i] = ismax[i] ? fmaxf(v[i], x) : (v[i] + x);
        }
    }
    if (l == 0) {
#pragma unroll
        for (int i = 0; i < NV; i++) s[w * 8 + i] = v[i];
    }
    __syncthreads();
    if (w == 0) {
        float t[NV];
#pragma unroll
        for (int i = 0; i < NV; i++) t[i] = s[l * 8 + i];   // 32 warp partials
#pragma unroll
        for (int i = 0; i < NV; i++) {
#pragma unroll
            for (int o = 16; o > 0; o >>= 1) {
                const float x = __shfl_xor_sync(0xffffffffu, t[i], o);
                t[i] = ismax[i] ? fmaxf(t[i], x) : (t[i] + x);
            }
        }
        if (l == 0) {
#pragma unroll
            for (int i = 0; i < NV; i++) s[i] = t[i];
        }
    }
    __syncthreads();
#pragma unroll
    for (int i = 0; i < NV; i++) v[i] = s[i];
    __syncthreads();
}

__global__ void __launch_bounds__(1024) epilogue_kernel(
    const void* __restrict__ isctl, const void* __restrict__ pad,
    const void* __restrict__ vis, float* __restrict__ out)
{
    __shared__ float s[32 * 8];
    __shared__ int   s_mode;
    const int bt   = blockIdx.x;
    const int b    = bt >> 2;
    const int tid  = threadIdx.x;
    constexpr int K = N_ / 1024;   // 4

    // ---------- preamble: everything independent of dist output ------------
    const int mode = detect_mode_block((const unsigned char*)pad, tid, &s_mode);
    bool mk[K];
#pragma unroll
    for (int k = 0; k < K; k++) {
        const int n = tid + k * 1024;
        mk[k] = !ldmask(isctl, b * N_ + n, mode)
              &&  ldmask(pad,   b * N_ + n, mode)
              &&  ldmask(vis,  bt * N_ + n, mode);
    }

    // ---------- wait for dist grid completion (memory visible) -------------
    asm volatile("griddepcontrol.wait;" ::: "memory");

    float hp[K], ht[K];
    float v5[5] = {0.f, 0.f, 0.f, -3.0e38f, -3.0e38f};  // nv,cdp,cdt,mxp,mxt
#pragma unroll
    for (int k = 0; k < K; k++) {
        const int n = tid + k * 1024;
        const float mp = fmaxf(dec_desc(g_enc_p[bt][n]), 0.0f);
        const float mt = fmaxf(dec_desc(g_enc_t[bt][n]), 0.0f);
        g_enc_p[bt][n] = 0u;                  // clean for next call
        g_enc_t[bt][n] = 0u;
        if (mk[k]) {
            v5[0] += 1.0f;
            v5[1] += (mp > THRESHF) ? 0.0f : mp;
            v5[2] += (mt > THRESHF) ? 0.0f : mt;
            hp[k] = fminf(mp, THRESHF);
            ht[k] = fminf(mt, THRESHF);
            v5[3] = fmaxf(v5[3], hp[k]);
            v5[4] = fmaxf(v5[4], ht[k]);
        } else { hp[k] = 0.f; ht[k] = 0.f; }
    }
    const bool m5[5] = {false, false, false, true, true};
    blockRedN<5>(v5, m5, s);
    const float nvT = v5[0], cdpT = v5[1], cdtT = v5[2];
    const float Mp  = v5[3], Mt   = v5[4];
    const bool  anyv = (Mp > -1.0e30f);

    float v4[4] = {0.f, 0.f, 0.f, 0.f};       // sep, shp, set, sht
#pragma unroll
    for (int k = 0; k < K; k++) {
        if (mk[k]) {
            const float e1 = expf((hp[k] - Mp) * INV_TEMP);
            const float e2 = expf((ht[k] - Mt) * INV_TEMP);
            v4[0] += e1; v4[1] += hp[k] * e1;
            v4[2] += e2; v4[3] += ht[k] * e2;
        }
    }
    const bool m4[4] = {false, false, false, false};
    blockRedN<4>(v4, m4, s);

    if (tid == 0) {
        const float nvc = fmaxf(nvT, 1.0f);
        g_cd[bt] = cdpT / nvc + cdtT / nvc;
        const float rp = anyv ? (v4[1] / v4[0]) : 0.0f;
        const float rt = anyv ? (v4[3] / v4[2]) : 0.0f;
        g_hd[bt] = fmaxf(rp, rt);
        __threadfence();
        const unsigned rank = atomicAdd(&g_done, 1u);
        if (rank == BT_ - 1) {                // last block: fixed-order combine
            __threadfence();
            float cd = 0.f, hd = 0.f;
#pragma unroll
            for (int i = 0; i < BT_; i++) { cd += g_cd[i]; hd += g_hd[i]; }
            out[0] = ALPHA_C * (cd / (float)BT_)
                   + (1.0f - ALPHA_C) * (hd / (float)BT_);
            g_done = 0u;                      // reset for next call
        }
    }
}

// ---------------------------------------------------------------------------
extern "C" void kernel_launch(void* const* d_in, const int* in_sizes, int n_in,
                              void* d_out, int out_size) {
    const float* pred = (const float*)d_in[0];
    const float* tgt  = (const float*)d_in[1];
    const void*  isc  = d_in[2];
    const void*  pad  = d_in[3];
    const void*  vis  = d_in[4];
    float*       out  = (float*)d_out;

    dist_kernel<<<dim3(ROWBLKS, COLBLKS, BT_ * 2), 128>>>(
        pred, tgt, isc, pad, vis);

    // PDL dependent launch: epilogue may start while dist drains; it gates
    // itself with griddepcontrol.wait before reading dist output.
    cudaLaunchConfig_t cfg = {};
    cfg.gridDim  = dim3(BT_);
    cfg.blockDim = dim3(1024);
    cudaLaunchAttribute attr[1];
    attr[0].id = cudaLaunchAttributeProgrammaticStreamSerialization;
    attr[0].val.programmaticStreamSerializationAllowed = 1;
    cfg.attrs = attr;
    cfg.numAttrs = 1;
    cudaLaunchKernelEx(&cfg, epilogue_kernel, isc, pad, vis, out);
}

// round 16
// speedup vs baseline: 1.0755x; 1.0755x over previous
#include <cuda_runtime.h>

// ============================================================================
// HybridLoss: B=2, T=4, N=4096  —  2 launches with PDL overlap.
// DIST (dual-pass, zero-shuffle, SCALAR inner loop): block = 1024 rows x
//   256 cols, 128 thr; grid (4,16,16) = 1024 blocks (~7/SM, R14 optimum).
//   pass 0: rows=pred, cols=tgt  -> row-min = min_p -> g_enc_p
//   pass 1: rows=tgt,  cols=pred -> row-min = min_t -> g_enc_t
//   Row bias rw added ONCE at publish: 3 FFMA + 1 FMNMX per distance.
// EPILOGUE: grid 8 x 1024 thr, PDL dependent; fused multi-value reductions.
// All device state zero at load and re-zeroed each call (graph-safe).
// ============================================================================

#define ALPHA_C  0.5f
#define INV_TEMP 10.0f
#define BIGF     10000000000.0f
#define THRESHF  1000000000.0f

constexpr int N_  = 4096;
constexpr int BT_ = 8;

constexpr int ROWS_PB = 1024;             // rows per block
constexpr int COLS_PB = 256;              // cols per block (staged once)
constexpr int RPT     = 8;                // rows per thread
constexpr int ROWBLKS = N_ / ROWS_PB;     // 4
constexpr int COLBLKS = N_ / COLS_PB;     // 16

__device__ unsigned g_enc_p[BT_][N_];
__device__ unsigned g_enc_t[BT_][N_];
__device__ float    g_cd[BT_];
__device__ float    g_hd[BT_];
__device__ unsigned g_done;

// ---------------------------------------------------------------------------
__device__ __forceinline__ unsigned enc_desc(float f) {
    unsigned b = __float_as_uint(f);
    unsigned asc = (b & 0x80000000u) ? ~b : (b | 0x80000000u);
    return ~asc;
}
__device__ __forceinline__ float dec_desc(unsigned k) {
    unsigned asc = ~k;
    unsigned b = (asc & 0x80000000u) ? (asc ^ 0x80000000u) : ~asc;
    return __uint_as_float(b);
}

__device__ __forceinline__ bool ldmask(const void* p, int i, int mode) {
    if (mode == 0) return ((const unsigned char*)p)[i] != 0;
    if (mode == 1) return ((const int*)p)[i] != 0;
    return ((const float*)p)[i] != 0.0f;
}

// Per-block mask-dtype detection (warp-0 ballot of 32 samples of the ~95%-
// dense padding mask). P(all 32 sampled bytes zero for u8 bool) ~ 0.05^32.
__device__ __forceinline__ int detect_mode_block(const unsigned char* pad,
                                                 int tid, int* s_mode) {
    if (tid < 32) {
        const unsigned b1 = __ballot_sync(0xffffffffu, pad[4 * tid + 1] != 0);
        const unsigned b2 = __ballot_sync(0xffffffffu, pad[4 * tid + 2] != 0);
        if (tid == 0) *s_mode = b1 ? 0 : (b2 ? 2 : 1);
    }
    __syncthreads();
    return *s_mode;
}

// ---------------------------------------------------------------------------
// dist: grid (ROWBLKS, COLBLKS, BT_*2), 128 threads.
// ---------------------------------------------------------------------------
__global__ void __launch_bounds__(128) dist_kernel(
    const float* __restrict__ pred, const float* __restrict__ tgt,
    const void* __restrict__ isctl, const void* __restrict__ pad,
    const void* __restrict__ vis)
{
    asm volatile("griddepcontrol.launch_dependents;");

    __shared__ float4 sc[COLS_PB];      // per col: (-2x, -2y, -2z, cw)
    __shared__ int    s_mode;

    const int rowblk = blockIdx.x;
    const int colblk = blockIdx.y;
    const int bt     = blockIdx.z >> 1;
    const int pass   = blockIdx.z & 1;
    const int b      = bt >> 2;
    const int tid    = threadIdx.x;
    const int mode   = detect_mode_block((const unsigned char*)pad, tid, &s_mode);

    const float* __restrict__ rows = pass ? tgt  : pred;
    const float* __restrict__ cols = pass ? pred : tgt;
    unsigned* __restrict__ enc = pass ? &g_enc_t[bt][0] : &g_enc_p[bt][0];

    // ---- stage this block's 256 columns (once) -----------------------------
#pragma unroll
    for (int c = tid; c < COLS_PB; c += 128) {
        const int m = colblk * COLS_PB + c;
        const float* cp = cols + ((size_t)bt * N_ + m) * 3;
        const float x = cp[0], y = cp[1], z = cp[2];
        const bool msk = !ldmask(isctl, b * N_ + m, mode)
                       &&  ldmask(pad,   b * N_ + m, mode)
                       &&  ldmask(vis,  bt * N_ + m, mode);
        const float cw = fmaf(x, x, fmaf(y, y, z * z)) + (msk ? 0.0f : BIGF);
        sc[c] = make_float4(-2.f * x, -2.f * y, -2.f * z, cw);
    }

    // ---- this thread's 8 rows (scalar); rw deferred to publish -------------
    float px[RPT], py[RPT], pz[RPT], rw[RPT], rmin[RPT];
    const int rbase = rowblk * ROWS_PB + tid * RPT;
#pragma unroll
    for (int r = 0; r < RPT; r++) {
        const int row = rbase + r;
        const float* rp = rows + ((size_t)bt * N_ + row) * 3;
        px[r] = rp[0]; py[r] = rp[1]; pz[r] = rp[2];
        const bool msk = !ldmask(isctl, b * N_ + row, mode)
                       &&  ldmask(pad,   b * N_ + row, mode)
                       &&  ldmask(vis,  bt * N_ + row, mode);
        rw[r] = fmaf(px[r], px[r], fmaf(py[r], py[r], pz[r] * pz[r]))
              + (msk ? 0.0f : BIGF);
        rmin[r] = 3.0e38f;
    }
    __syncthreads();   // the only barrier

    // ---- pure streaming loop: 256 cols x 8 rows, 3 FFMA + 1 FMNMX / dist ---
#pragma unroll 4
    for (int c = 0; c < COLS_PB; c++) {
        const float4 cv = sc[c];
#pragma unroll
        for (int r = 0; r < RPT; r++) {
            const float u = fmaf(px[r], cv.x,
                            fmaf(py[r], cv.y,
                            fmaf(pz[r], cv.z, cv.w)));
            rmin[r] = fminf(rmin[r], u);
        }
    }

    // ---- publish 8 row-mins (row bias added once, outside the loop) --------
#pragma unroll
    for (int r = 0; r < RPT; r++)
        atomicMax(&enc[rbase + r], enc_desc(rmin[r] + rw[r]));
}

// ---------------------------------------------------------------------------
// epilogue (PDL dependent): grid=8 (bt), 1024 threads.
// Fused multi-value block reductions: one smem round handles up to 5 values.
// ---------------------------------------------------------------------------
template <int NV>
__device__ __forceinline__ void blockRedN(float* v, const bool* ismax, float* s) {
    const int w = threadIdx.x >> 5, l = threadIdx.x & 31;
#pragma unroll
    for (int i = 0; i < NV; i++) {
#pragma unroll
        for (int o = 16; o > 0; o >>= 1) {
            const float x = __shfl_xor_sync(0xffffffffu, v[i], o);
            v[i] = ismax[i] ? fmaxf(v[i], x) : (v[i] + x);
        }
    }
    if (l == 0) {
#pragma unroll
        for (int i = 0; i < NV; i++) s[w * 8 + i] = v[i];
    }
    __syncthreads();
    if (w == 0) {
        float t[NV];
#pragma unroll
        for (int i = 0; i < NV; i++) t[i] = s[l * 8 + i];   // 32 warp partials
#pragma unroll
        for (int i = 0; i < NV; i++) {
#pragma unroll
            for (int o = 16; o > 0; o >>= 1) {
                const float x = __shfl_xor_sync(0xffffffffu, t[i], o);
                t[i] = ismax[i] ? fmaxf(t[i], x) : (t[i] + x);
            }
        }
        if (l == 0) {
#pragma unroll
            for (int i = 0; i < NV; i++) s[i] = t[i];
        }
    }
    __syncthreads();
#pragma unroll
    for (int i = 0; i < NV; i++) v[i] = s[i];
    __syncthreads();
}

__global__ void __launch_bounds__(1024) epilogue_kernel(
    const void* __restrict__ isctl, const void* __restrict__ pad,
    const void* __restrict__ vis, float* __restrict__ out)
{
    __shared__ float s[32 * 8];
    __shared__ int   s_mode;
    const int bt   = blockIdx.x;
    const int b    = bt >> 2;
    const int tid  = threadIdx.x;
    constexpr int K = N_ / 1024;   // 4

    // ---------- preamble: everything independent of dist output ------------
    const int mode = detect_mode_block((const unsigned char*)pad, tid, &s_mode);
    bool mk[K];
#pragma unroll
    for (int k = 0; k < K; k++) {
        const int n = tid + k * 1024;
        mk[k] = !ldmask(isctl, b * N_ + n, mode)
              &&  ldmask(pad,   b * N_ + n, mode)
              &&  ldmask(vis,  bt * N_ + n, mode);
    }

    // ---------- wait for dist grid completion (memory visible) -------------
    asm volatile("griddepcontrol.wait;" ::: "memory");

    float hp[K], ht[K];
    float v5[5] = {0.f, 0.f, 0.f, -3.0e38f, -3.0e38f};  // nv,cdp,cdt,mxp,mxt
#pragma unroll
    for (int k = 0; k < K; k++) {
        const int n = tid + k * 1024;
        const float mp = fmaxf(dec_desc(g_enc_p[bt][n]), 0.0f);
        const float mt = fmaxf(dec_desc(g_enc_t[bt][n]), 0.0f);
        g_enc_p[bt][n] = 0u;                  // clean for next call
        g_enc_t[bt][n] = 0u;
        if (mk[k]) {
            v5[0] += 1.0f;
            v5[1] += (mp > THRESHF) ? 0.0f : mp;
            v5[2] += (mt > THRESHF) ? 0.0f : mt;
            hp[k] = fminf(mp, THRESHF);
            ht[k] = fminf(mt, THRESHF);
            v5[3] = fmaxf(v5[3], hp[k]);
            v5[4] = fmaxf(v5[4], ht[k]);
        } else { hp[k] = 0.f; ht[k] = 0.f; }
    }
    const bool m5[5] = {false, false, false, true, true};
    blockRedN<5>(v5, m5, s);
    const float nvT = v5[0], cdpT = v5[1], cdtT = v5[2];
    const float Mp  = v5[3], Mt   = v5[4];
    const bool  anyv = (Mp > -1.0e30f);

    float v4[4] = {0.f, 0.f, 0.f, 0.f};       // sep, shp, set, sht
#pragma unroll
    for (int k = 0; k < K; k++) {
        if (mk[k]) {
            const float e1 = expf((hp[k] - Mp) * INV_TEMP);
            const float e2 = expf((ht[k] - Mt) * INV_TEMP);
            v4[0] += e1; v4[1] += hp[k] * e1;
            v4[2] += e2; v4[3] += ht[k] * e2;
        }
    }
    const bool m4[4] = {false, false, false, false};
    blockRedN<4>(v4, m4, s);

    if (tid == 0) {
        const float nvc = fmaxf(nvT, 1.0f);
        g_cd[bt] = cdpT / nvc + cdtT / nvc;
        const float rp = anyv ? (v4[1] / v4[0]) : 0.0f;
        const float rt = anyv ? (v4[3] / v4[2]) : 0.0f;
        g_hd[bt] = fmaxf(rp, rt);
        __threadfence();
        const unsigned rank = atomicAdd(&g_done, 1u);
        if (rank == BT_ - 1) {                // last block: fixed-order combine
            __threadfence();
            float cd = 0.f, hd = 0.f;
#pragma unroll
            for (int i = 0; i < BT_; i++) { cd += g_cd[i]; hd += g_hd[i]; }
            out[0] = ALPHA_C * (cd / (float)BT_)
                   + (1.0f - ALPHA_C) * (hd / (float)BT_);
            g_done = 0u;                      // reset for next call
        }
    }
}

// ---------------------------------------------------------------------------
extern "C" void kernel_launch(void* const* d_in, const int* in_sizes, int n_in,
                              void* d_out, int out_size) {
    const float* pred = (const float*)d_in[0];
    const float* tgt  = (const float*)d_in[1];
    const void*  isc  = d_in[2];
    const void*  pad  = d_in[3];
    const void*  vis  = d_in[4];
    float*       out  = (float*)d_out;

    dist_kernel<<<dim3(ROWBLKS, COLBLKS, BT_ * 2), 128>>>(
        pred, tgt, isc, pad, vis);

    // PDL dependent launch: epilogue may start while dist drains; it gates
    // itself with griddepcontrol.wait before reading dist output.
    cudaLaunchConfig_t cfg = {};
    cfg.gridDim  = dim3(BT_);
    cfg.blockDim = dim3(1024);
    cudaLaunchAttribute attr[1];
    attr[0].id = cudaLaunchAttributeProgrammaticStreamSerialization;
    attr[0].val.programmaticStreamSerializationAllowed = 1;
    cfg.attrs = attr;
    cfg.numAttrs = 1;
    cudaLaunchKernelEx(&cfg, epilogue_kernel, isc, pad, vis, out);
}